// round 11
// baseline (speedup 1.0000x reference)
#include <cuda_runtime.h>
#include <cuda_fp16.h>
#include <math.h>

#define N_NODES 20000
#define NHID 128
#define HEADS 4
#define HC (HEADS * NHID)          // 512
#define E_EDGES 320000
#define ETOT (E_EDGES + N_NODES)   // 340000
#define NLAYERS 4
#define NCLASS 40
#define NEG_SLOPE 0.2f
#define DT 1.0f
#define ALPHA 1.0f
#define GAMMA 1.0f

// d_out layout: [out (N*NCLASS)] [X_all (N*(L+1)*C)] [Y_all (N*(L+1)*C)]
#define OUT_OFF   0
#define XALL_OFF  (N_NODES * NCLASS)
#define YALL_OFF  (XALL_OFF + N_NODES * (NLAYERS + 1) * NHID)
#define LSTRIDE   ((NLAYERS + 1) * NHID)

// ------------------------- device scratch (no allocs allowed) ----------------
__device__ __half g_hh[N_NODES * HC];        // fp16 messages
__device__ float  g_X[N_NODES * NHID];
__device__ float  g_Y[N_NODES * NHID];
__device__ __half g_Xhi[N_NODES * NHID];     // double-fp16 split X (GEMM A)
__device__ __half g_Xlo[N_NODES * NHID];
__device__ __half g_Whi[HC * NHID];          // split W, TRANSPOSED [n][k]
__device__ __half g_Wlo[HC * NHID];
__device__ float  g_as[N_NODES * HEADS];
__device__ float  g_ad[N_NODES * HEADS];
__device__ int    g_deg[N_NODES];
__device__ int    g_cursor[N_NODES];
__device__ int    g_off[N_NODES + 1];
__device__ int    g_csr_src[ETOT];

__device__ __forceinline__ void mma_f16(float* c, const unsigned* a, const unsigned* b) {
    asm volatile(
        "mma.sync.aligned.m16n8k16.row.col.f32.f16.f16.f32 "
        "{%0,%1,%2,%3}, {%4,%5,%6,%7}, {%8,%9}, {%0,%1,%2,%3};\n"
        : "+f"(c[0]), "+f"(c[1]), "+f"(c[2]), "+f"(c[3])
        : "r"(a[0]), "r"(a[1]), "r"(a[2]), "r"(a[3]), "r"(b[0]), "r"(b[1]));
}

__device__ __forceinline__ void cp_async16(void* smem_dst, const void* gmem_src, bool valid) {
    unsigned sm = (unsigned)__cvta_generic_to_shared(smem_dst);
    int sz = valid ? 16 : 0;
    asm volatile("cp.async.cg.shared.global [%0], [%1], 16, %2;\n"
                 :: "r"(sm), "l"(gmem_src), "r"(sz));
}
#define CP_COMMIT() asm volatile("cp.async.commit_group;\n" ::: "memory")
#define CP_WAIT(n)  asm volatile("cp.async.wait_group %0;\n" :: "n"(n) : "memory")

// ------------------------- setup kernels -------------------------------------
// split W (fp16 hi/lo, transposed to [n][k]) + zero deg/cursor. 65536 threads.
__global__ void k_splitW(const float* __restrict__ W) {
    int i = blockIdx.x * blockDim.x + threadIdx.x;   // 0..65535
    float w = W[i];
    __half hi = __float2half_rn(w);
    __half lo = __float2half_rn(w - __half2float(hi));
    int k = i >> 9;          // W is [128][512] row-major
    int n = i & 511;
    g_Whi[n * NHID + k] = hi;
    g_Wlo[n * NHID + k] = lo;
    if (i < N_NODES) { g_deg[i] = 0; g_cursor[i] = 0; }
}

__global__ void k_count_deg(const int* __restrict__ dst) {
    int e = blockIdx.x * blockDim.x + threadIdx.x;
    if (e >= ETOT) return;
    int d = (e < E_EDGES) ? dst[e] : (e - E_EDGES);
    atomicAdd(&g_deg[d], 1);
}

__global__ void k_scan() {
    __shared__ int s[1024];
    const int CH = (N_NODES + 1023) / 1024;
    int tid = threadIdx.x;
    int base = tid * CH;
    int sum = 0;
    for (int i = 0; i < CH; i++) {
        int idx = base + i;
        if (idx < N_NODES) sum += g_deg[idx];
    }
    s[tid] = sum;
    __syncthreads();
    for (int d = 1; d < 1024; d <<= 1) {
        int v = (tid >= d) ? s[tid - d] : 0;
        __syncthreads();
        s[tid] += v;
        __syncthreads();
    }
    int run = (tid == 0) ? 0 : s[tid - 1];
    for (int i = 0; i < CH; i++) {
        int idx = base + i;
        if (idx < N_NODES) { g_off[idx] = run; run += g_deg[idx]; }
    }
    if (tid == 1023) g_off[N_NODES] = run;
}

__global__ void k_scatter(const int* __restrict__ src, const int* __restrict__ dst) {
    int e = blockIdx.x * blockDim.x + threadIdx.x;
    if (e >= ETOT) return;
    int d, s;
    if (e < E_EDGES) { d = dst[e]; s = src[e]; }
    else { d = e - E_EDGES; s = d; }
    int pos = g_off[d] + atomicAdd(&g_cursor[d], 1);
    g_csr_src[pos] = s;
}

// init state (+ split X to fp16 hi/lo) + write layer-0 slices
__global__ void k_init(const float* __restrict__ x, float* __restrict__ out) {
    int n = blockIdx.x;
    int t = threadIdx.x;
    float v = x[n * NHID + t];
    g_X[n * NHID + t] = v;
    g_Y[n * NHID + t] = v;
    __half hi = __float2half_rn(v);
    g_Xhi[n * NHID + t] = hi;
    g_Xlo[n * NHID + t] = __float2half_rn(v - __half2float(hi));
    out[XALL_OFF + n * LSTRIDE + t] = v;
    out[YALL_OFF + n * LSTRIDE + t] = v;
}

// ------------------------- 3x split-FP16 tensor GEMM + fused attention --------
// C = X @ W, 128x128 tile, BK=32 halves, m16n8k16 f16 MMA, fp32 accum.
// cp.async double-buffered pipeline: stage st+1 loads overlap stage st MMAs.
// Dynamic smem 2 stages x 4 buffers x 128x40 halves = 80 KB; 2 CTAs/SM.
#define GBM 128
#define GBN 128
#define APH 40                                    // pitch in halves
#define BUF_H (128 * APH)                         // halves per buffer
#define STAGE_H (4 * BUF_H)                       // halves per stage
#define GEMM_SMEM (2 * STAGE_H * 2)               // bytes = 81920

__global__ __launch_bounds__(256, 2) void k_gemm(const float* __restrict__ att_src,
                                                 const float* __restrict__ att_dst) {
    extern __shared__ __half smh[];

    int tid = threadIdx.x;
    int m0 = blockIdx.y * GBM;
    int n0 = blockIdx.x * GBN;      // = head * NHID
    int head = blockIdx.x;
    int warp = tid >> 5, lane = tid & 31;
    int g = lane >> 2, q = lane & 3;
    int wm = (warp >> 1) * 32;      // warp tile 32(m) x 64(n)
    int wn = (warp & 1) * 64;

    float acc[2][8][4];
#pragma unroll
    for (int mi = 0; mi < 2; mi++)
#pragma unroll
        for (int ni = 0; ni < 8; ni++)
#pragma unroll
            for (int j = 0; j < 4; j++) acc[mi][ni][j] = 0.f;

    // per-thread stage-load coordinates (2 chunks of 16B per buffer)
    int r0 = tid >> 1;                       // rows handled: r0 (c8 = 2*(tid&1)..)
    // simpler: idx scheme identical to R10: idx = tid + i*256, r = idx>>2, c8 = idx&3
    // issue cp.async for one stage into buffer `buf`
    auto load_stage = [&](int buf, int st) {
        __half* Ah = smh + buf * STAGE_H;
        __half* Al = Ah + BUF_H;
        __half* Bh = Al + BUF_H;
        __half* Bl = Bh + BUF_H;
#pragma unroll
        for (int i = 0; i < 2; i++) {
            int idx = tid + i * 256;         // 0..511
            int r = idx >> 2, c8 = idx & 3;
            bool av = (m0 + r < N_NODES);
            const __half* gah = g_Xhi + (m0 + r) * NHID + st * 32 + c8 * 8;
            const __half* gal = g_Xlo + (m0 + r) * NHID + st * 32 + c8 * 8;
            cp_async16(&Ah[r * APH + c8 * 8], gah, av);
            cp_async16(&Al[r * APH + c8 * 8], gal, av);
            const __half* gbh = g_Whi + (n0 + r) * NHID + st * 32 + c8 * 8;
            const __half* gbl = g_Wlo + (n0 + r) * NHID + st * 32 + c8 * 8;
            cp_async16(&Bh[r * APH + c8 * 8], gbh, true);
            cp_async16(&Bl[r * APH + c8 * 8], gbl, true);
        }
    };
    (void)r0;

    load_stage(0, 0);
    CP_COMMIT();

    for (int st = 0; st < 4; st++) {
        if (st < 3) {
            load_stage((st + 1) & 1, st + 1);
            CP_COMMIT();
            CP_WAIT(1);
        } else {
            CP_WAIT(0);
        }
        __syncthreads();

        const __half* Ah = smh + (st & 1) * STAGE_H;
        const __half* Al = Ah + BUF_H;
        const __half* Bh = Al + BUF_H;
        const __half* Bl = Bh + BUF_H;

#pragma unroll
        for (int ks = 0; ks < 2; ks++) {
            int kb = ks * 16;
            unsigned ah[2][4], al[2][4];
#pragma unroll
            for (int mi = 0; mi < 2; mi++) {
                int r = wm + mi * 16 + g;
                ah[mi][0] = *(const unsigned*)&Ah[r * APH + kb + 2 * q];
                ah[mi][1] = *(const unsigned*)&Ah[(r + 8) * APH + kb + 2 * q];
                ah[mi][2] = *(const unsigned*)&Ah[r * APH + kb + 2 * q + 8];
                ah[mi][3] = *(const unsigned*)&Ah[(r + 8) * APH + kb + 2 * q + 8];
                al[mi][0] = *(const unsigned*)&Al[r * APH + kb + 2 * q];
                al[mi][1] = *(const unsigned*)&Al[(r + 8) * APH + kb + 2 * q];
                al[mi][2] = *(const unsigned*)&Al[r * APH + kb + 2 * q + 8];
                al[mi][3] = *(const unsigned*)&Al[(r + 8) * APH + kb + 2 * q + 8];
            }
#pragma unroll
            for (int ni = 0; ni < 8; ni++) {
                int c = wn + ni * 8 + g;
                unsigned bh[2], bl[2];
                bh[0] = *(const unsigned*)&Bh[c * APH + kb + 2 * q];
                bh[1] = *(const unsigned*)&Bh[c * APH + kb + 2 * q + 8];
                bl[0] = *(const unsigned*)&Bl[c * APH + kb + 2 * q];
                bl[1] = *(const unsigned*)&Bl[c * APH + kb + 2 * q + 8];
#pragma unroll
                for (int mi = 0; mi < 2; mi++) {
                    mma_f16(acc[mi][ni], ah[mi], bh);   // hi*hi
                    mma_f16(acc[mi][ni], ah[mi], bl);   // hi*lo
                    mma_f16(acc[mi][ni], al[mi], bh);   // lo*hi
                }
            }
        }
        __syncthreads();
    }

    // epilogue scratch: reuse stage-0 region
    float* sAs = (float*)smh;            // [2][128]
    float* sAd = ((float*)smh) + 256;

    float attS[16], attD[16];
#pragma unroll
    for (int ni = 0; ni < 8; ni++) {
        int c = n0 + wn + ni * 8 + 2 * q;
        attS[2 * ni] = att_src[c];     attS[2 * ni + 1] = att_src[c + 1];
        attD[2 * ni] = att_dst[c];     attD[2 * ni + 1] = att_dst[c + 1];
    }
#pragma unroll
    for (int mi = 0; mi < 2; mi++) {
        float s1a = 0.f, s2a = 0.f, s1b = 0.f, s2b = 0.f;
#pragma unroll
        for (int ni = 0; ni < 8; ni++) {
            s1a += acc[mi][ni][0] * attS[2 * ni] + acc[mi][ni][1] * attS[2 * ni + 1];
            s2a += acc[mi][ni][0] * attD[2 * ni] + acc[mi][ni][1] * attD[2 * ni + 1];
            s1b += acc[mi][ni][2] * attS[2 * ni] + acc[mi][ni][3] * attS[2 * ni + 1];
            s2b += acc[mi][ni][2] * attD[2 * ni] + acc[mi][ni][3] * attD[2 * ni + 1];
        }
#pragma unroll
        for (int o = 2; o; o >>= 1) {
            s1a += __shfl_down_sync(0xffffffffu, s1a, o, 4);
            s2a += __shfl_down_sync(0xffffffffu, s2a, o, 4);
            s1b += __shfl_down_sync(0xffffffffu, s1b, o, 4);
            s2b += __shfl_down_sync(0xffffffffu, s2b, o, 4);
        }
        if (q == 0) {
            int half = warp & 1;
            int rA = wm + mi * 16 + g;
            sAs[half * 128 + rA] = s1a;      sAd[half * 128 + rA] = s2a;
            sAs[half * 128 + rA + 8] = s1b;  sAd[half * 128 + rA + 8] = s2b;
        }
    }
    __syncthreads();
    if (tid < 128) {
        int r = m0 + tid;
        if (r < N_NODES) {
            g_as[r * HEADS + head] = sAs[tid] + sAs[128 + tid];
            g_ad[r * HEADS + head] = sAd[tid] + sAd[128 + tid];
        }
    }

    // store h as fp16
#pragma unroll
    for (int mi = 0; mi < 2; mi++) {
        int r = m0 + wm + mi * 16 + g;
#pragma unroll
        for (int ni = 0; ni < 8; ni++) {
            int c = n0 + wn + ni * 8 + 2 * q;
            if (r < N_NODES)
                *((__half2*)(g_hh + r * HC + c)) = __floats2half2_rn(acc[mi][ni][0], acc[mi][ni][1]);
            if (r + 8 < N_NODES)
                *((__half2*)(g_hh + (r + 8) * HC + c)) = __floats2half2_rn(acc[mi][ni][2], acc[mi][ni][3]);
        }
    }
}

// ------------------------- fused softmax + aggregate + GraphCON update --------
// 64 threads/node; thread t owns fp16 flat channels [8t..8t+7] (head t/16).
#define ACH 64
__global__ __launch_bounds__(64) void k_aggregate(const float* __restrict__ bias,
                                                  float* __restrict__ out, int layer) {
    __shared__ int   s_src[ACH];
    __shared__ float s_ex[ACH * 4];
    __shared__ float4 s_den[2];

    int n = blockIdx.x;
    int t = threadIdx.x;
    int hd = t >> 4;
    int wid = t >> 5, lane = t & 31;
    int st = g_off[n], en = g_off[n + 1];
    float4 ad4 = ((const float4*)g_ad)[n];
    const uint4* h16 = (const uint4*)g_hh;

    float4 denp = make_float4(0.f, 0.f, 0.f, 0.f);
    float a0 = 0.f, a1 = 0.f, a2 = 0.f, a3 = 0.f;
    float a4 = 0.f, a5 = 0.f, a6 = 0.f, a7 = 0.f;

#define ACCUM(u, e) { \
    float2 p0 = __half22float2(*(const __half2*)&u.x); \
    float2 p1 = __half22float2(*(const __half2*)&u.y); \
    float2 p2 = __half22float2(*(const __half2*)&u.z); \
    float2 p3 = __half22float2(*(const __half2*)&u.w); \
    a0 += e * p0.x; a1 += e * p0.y; a2 += e * p1.x; a3 += e * p1.y; \
    a4 += e * p2.x; a5 += e * p2.y; a6 += e * p3.x; a7 += e * p3.y; }

    for (int c0 = st; c0 < en; c0 += ACH) {
        int cl = en - c0; if (cl > ACH) cl = ACH;
        if (t < cl) {
            int s = g_csr_src[c0 + t];
            float4 as4 = ((const float4*)g_as)[s];
            float e0 = as4.x + ad4.x, e1 = as4.y + ad4.y;
            float e2 = as4.z + ad4.z, e3 = as4.w + ad4.w;
            e0 = e0 > 0.f ? e0 : e0 * NEG_SLOPE;
            e1 = e1 > 0.f ? e1 : e1 * NEG_SLOPE;
            e2 = e2 > 0.f ? e2 : e2 * NEG_SLOPE;
            e3 = e3 > 0.f ? e3 : e3 * NEG_SLOPE;
            float x0 = __expf(e0), x1 = __expf(e1), x2 = __expf(e2), x3 = __expf(e3);
            s_src[t] = s;
            ((float4*)s_ex)[t] = make_float4(x0, x1, x2, x3);
            denp.x += x0; denp.y += x1; denp.z += x2; denp.w += x3;
        }
        __syncthreads();
        int j = 0;
        for (; j + 8 <= cl; j += 8) {
            int ss[8]; float ee[8]; uint4 uu[8];
#pragma unroll
            for (int u = 0; u < 8; u++) {
                ss[u] = s_src[j + u];
                ee[u] = s_ex[(j + u) * 4 + hd];
            }
#pragma unroll
            for (int u = 0; u < 8; u++) uu[u] = h16[ss[u] * 64 + t];
#pragma unroll
            for (int u = 0; u < 8; u++) ACCUM(uu[u], ee[u])
        }
        for (; j < cl; j++) {
            int s = s_src[j];
            float e = s_ex[j * 4 + hd];
            uint4 u = h16[s * 64 + t];
            ACCUM(u, e)
        }
        __syncthreads();
    }
#undef ACCUM

#pragma unroll
    for (int o = 16; o; o >>= 1) {
        denp.x += __shfl_xor_sync(0xffffffffu, denp.x, o);
        denp.y += __shfl_xor_sync(0xffffffffu, denp.y, o);
        denp.z += __shfl_xor_sync(0xffffffffu, denp.z, o);
        denp.w += __shfl_xor_sync(0xffffffffu, denp.w, o);
    }
    if (lane == 0) s_den[wid] = denp;
    __syncthreads();
    float4 d0 = s_den[0], d1 = s_den[1];
    float dens[4] = {d0.x + d1.x, d0.y + d1.y, d0.z + d1.z, d0.w + d1.w};
    float inv = 1.0f / dens[hd];

    const float4* b4p = (const float4*)(bias + 8 * t);
    float4 b0 = b4p[0], b1 = b4p[1];
    float g0 = a0 * inv + b0.x, g1 = a1 * inv + b0.y;
    float g2 = a2 * inv + b0.z, g3 = a3 * inv + b0.w;
    float g4 = a4 * inv + b1.x, g5 = a5 * inv + b1.y;
    float g6 = a6 * inv + b1.z, g7 = a7 * inv + b1.w;
    g0 = g0 > 0.f ? g0 : (expf(g0) - 1.f);
    g1 = g1 > 0.f ? g1 : (expf(g1) - 1.f);
    g2 = g2 > 0.f ? g2 : (expf(g2) - 1.f);
    g3 = g3 > 0.f ? g3 : (expf(g3) - 1.f);
    g4 = g4 > 0.f ? g4 : (expf(g4) - 1.f);
    g5 = g5 > 0.f ? g5 : (expf(g5) - 1.f);
    g6 = g6 > 0.f ? g6 : (expf(g6) - 1.f);
    g7 = g7 > 0.f ? g7 : (expf(g7) - 1.f);
    float aggA = 0.25f * (g0 + g1 + g2 + g3);
    float aggB = 0.25f * (g4 + g5 + g6 + g7);

    float2 xv = *((const float2*)(g_X + n * NHID + 2 * t));
    float2 yv = *((const float2*)(g_Y + n * NHID + 2 * t));
    float y2a = yv.x + DT * (aggA - ALPHA * yv.x - GAMMA * xv.x);
    float y2b = yv.y + DT * (aggB - ALPHA * yv.y - GAMMA * xv.y);
    float x2a = xv.x + DT * y2a;
    float x2b = xv.y + DT * y2b;
    *((float2*)(g_X + n * NHID + 2 * t)) = make_float2(x2a, x2b);
    *((float2*)(g_Y + n * NHID + 2 * t)) = make_float2(y2a, y2b);

    // split X to fp16 hi/lo for next layer's GEMM
    __half hA = __float2half_rn(x2a), hB = __float2half_rn(x2b);
    __half lA = __float2half_rn(x2a - __half2float(hA));
    __half lB = __float2half_rn(x2b - __half2float(hB));
    *((__half2*)(g_Xhi + n * NHID + 2 * t)) = __halves2half2(hA, hB);
    *((__half2*)(g_Xlo + n * NHID + 2 * t)) = __halves2half2(lA, lB);

    float* xo = out + XALL_OFF + n * LSTRIDE + (layer + 1) * NHID + 2 * t;
    float* yo = out + YALL_OFF + n * LSTRIDE + (layer + 1) * NHID + 2 * t;
    *((float2*)xo) = make_float2(x2a, x2b);
    *((float2*)yo) = make_float2(y2a, y2b);
}

// ------------------------- output projection ----------------------------------
__global__ void k_outproj(const float* __restrict__ Wr, const float* __restrict__ br,
                          float* __restrict__ out) {
    __shared__ float xs[NHID];
    int n = blockIdx.x;
    int t = threadIdx.x;
    xs[t] = g_X[n * NHID + t];
    __syncthreads();
    if (t < NCLASS) {
        const float* w = Wr + t * NHID;
        float acc = 0.f;
#pragma unroll 8
        for (int k = 0; k < NHID; k++) acc += xs[k] * w[k];
        out[OUT_OFF + n * NCLASS + t] = acc + br[t];
    }
}

// ------------------------- launch ---------------------------------------------
extern "C" void kernel_launch(void* const* d_in, const int* in_sizes, int n_in,
                              void* d_out, int out_size) {
    const float* x       = (const float*)d_in[0];
    const int*   src     = (const int*)d_in[1];
    const int*   dst     = (const int*)d_in[2];
    const float* W       = (const float*)d_in[3];
    const float* att_src = (const float*)d_in[4];
    const float* att_dst = (const float*)d_in[5];
    const float* bias    = (const float*)d_in[6];
    const float* Wr      = (const float*)d_in[7];
    const float* br      = (const float*)d_in[8];
    float* out = (float*)d_out;

    cudaFuncSetAttribute(k_gemm, cudaFuncAttributeMaxDynamicSharedMemorySize, GEMM_SMEM);

    dim3 ggrid(HC / GBN, (N_NODES + GBM - 1) / GBM);   // (4, 157)

    // gemm in capture slot 4 for ncu. deps: splitW zeros deg/cursor before
    // count; gemm needs splitW + init; agg needs scatter + gemm.
    k_splitW<<<(NHID * HC) / 256, 256>>>(W);                 // 1 (also zeros)
    k_init<<<N_NODES, NHID>>>(x, out);                       // 2
    k_count_deg<<<(ETOT + 255) / 256, 256>>>(dst);           // 3
    k_gemm<<<ggrid, 256, GEMM_SMEM>>>(att_src, att_dst);     // 4 (layer 0)
    k_scan<<<1, 1024>>>();                                   // 5
    k_scatter<<<(ETOT + 255) / 256, 256>>>(src, dst);        // 6
    k_aggregate<<<N_NODES, 64>>>(bias, out, 0);              // 7 (layer 0)

    for (int l = 1; l < NLAYERS; l++) {
        k_gemm<<<ggrid, 256, GEMM_SMEM>>>(att_src, att_dst);
        k_aggregate<<<N_NODES, 64>>>(bias, out, l);
    }
    k_outproj<<<N_NODES, 128>>>(Wr, br, out);
}

// round 12
// speedup vs baseline: 1.0276x; 1.0276x over previous
#include <cuda_runtime.h>
#include <cuda_fp16.h>
#include <math.h>

#define N_NODES 20000
#define NHID 128
#define HEADS 4
#define HC (HEADS * NHID)          // 512
#define E_EDGES 320000
#define ETOT (E_EDGES + N_NODES)   // 340000
#define NLAYERS 4
#define NCLASS 40
#define NEG_SLOPE 0.2f
#define DT 1.0f
#define ALPHA 1.0f
#define GAMMA 1.0f

// d_out layout: [out (N*NCLASS)] [X_all (N*(L+1)*C)] [Y_all (N*(L+1)*C)]
#define OUT_OFF   0
#define XALL_OFF  (N_NODES * NCLASS)
#define YALL_OFF  (XALL_OFF + N_NODES * (NLAYERS + 1) * NHID)
#define LSTRIDE   ((NLAYERS + 1) * NHID)

// ------------------------- device scratch (no allocs allowed) ----------------
__device__ __half g_hh[N_NODES * HC];        // fp16 messages
__device__ float  g_X[N_NODES * NHID];
__device__ float  g_Y[N_NODES * NHID];
__device__ __half g_Xhi[N_NODES * NHID];     // double-fp16 split X (GEMM A)
__device__ __half g_Xlo[N_NODES * NHID];
__device__ __half g_Whi[HC * NHID];          // split W, TRANSPOSED [n][k]
__device__ __half g_Wlo[HC * NHID];
__device__ float  g_as[N_NODES * HEADS];
__device__ float  g_ad[N_NODES * HEADS];
__device__ int    g_deg[N_NODES];
__device__ int    g_cursor[N_NODES];
__device__ int    g_off[N_NODES + 1];
__device__ int    g_csr_src[ETOT];
__device__ int    g_s1;                      // grid-sync flags for k_csr
__device__ int    g_s2;

__device__ __forceinline__ void mma_f16(float* c, const unsigned* a, const unsigned* b) {
    asm volatile(
        "mma.sync.aligned.m16n8k16.row.col.f32.f16.f16.f32 "
        "{%0,%1,%2,%3}, {%4,%5,%6,%7}, {%8,%9}, {%0,%1,%2,%3};\n"
        : "+f"(c[0]), "+f"(c[1]), "+f"(c[2]), "+f"(c[3])
        : "r"(a[0]), "r"(a[1]), "r"(a[2]), "r"(a[3]), "r"(b[0]), "r"(b[1]));
}

__device__ __forceinline__ void cp_async16(void* smem_dst, const void* gmem_src, bool valid) {
    unsigned sm = (unsigned)__cvta_generic_to_shared(smem_dst);
    int sz = valid ? 16 : 0;
    asm volatile("cp.async.cg.shared.global [%0], [%1], 16, %2;\n"
                 :: "r"(sm), "l"(gmem_src), "r"(sz));
}
#define CP_COMMIT() asm volatile("cp.async.commit_group;\n" ::: "memory")
#define CP_WAIT(n)  asm volatile("cp.async.wait_group %0;\n" :: "n"(n) : "memory")

// ------------------------- setup: splitW + init + zero (fused) ----------------
__global__ void k_setup(const float* __restrict__ x, const float* __restrict__ W,
                        float* __restrict__ out) {
    int n = blockIdx.x;          // 20000 blocks x 128 threads
    int t = threadIdx.x;
    float v = x[n * NHID + t];
    g_X[n * NHID + t] = v;
    g_Y[n * NHID + t] = v;
    __half hi = __float2half_rn(v);
    g_Xhi[n * NHID + t] = hi;
    g_Xlo[n * NHID + t] = __float2half_rn(v - __half2float(hi));
    out[XALL_OFF + n * LSTRIDE + t] = v;
    out[YALL_OFF + n * LSTRIDE + t] = v;
    if (n < 512) {               // W split: 512*128 = 65536 elements
        int i = n * 128 + t;
        float w = W[i];
        __half whi = __float2half_rn(w);
        g_Whi[(i & 511) * NHID + (i >> 9)] = whi;
        g_Wlo[(i & 511) * NHID + (i >> 9)] = __float2half_rn(w - __half2float(whi));
    }
    if (t == 0) { g_deg[n] = 0; g_cursor[n] = 0; }
    if (n == 0 && t == 0) { g_s1 = 0; g_s2 = 0; }
}

// ------------------------- CSR build in ONE kernel (all-resident grid) --------
// 148 blocks x 256 threads = exactly one wave -> every block resident, so the
// flag-based grid syncs cannot deadlock.
#define CSR_BLOCKS 148
#define CSR_THREADS 256
__global__ __launch_bounds__(CSR_THREADS) void k_csr(const int* __restrict__ src,
                                                     const int* __restrict__ dst) {
    int t = threadIdx.x;
    int gt = blockIdx.x * CSR_THREADS + t;
    const int STRIDE = CSR_BLOCKS * CSR_THREADS;

    // phase 1: count degrees
    for (int e = gt; e < ETOT; e += STRIDE) {
        int d = (e < E_EDGES) ? dst[e] : (e - E_EDGES);
        atomicAdd(&g_deg[d], 1);
    }
    __threadfence();
    __syncthreads();
    if (t == 0) {
        atomicAdd(&g_s1, 1);
        while (*(volatile int*)&g_s1 < CSR_BLOCKS) { }
    }
    __syncthreads();

    // phase 2: block 0 scans
    if (blockIdx.x == 0) {
        __shared__ int sh[CSR_THREADS];
        const int CH = (N_NODES + CSR_THREADS - 1) / CSR_THREADS;  // 79
        int base = t * CH;
        int sum = 0;
        for (int i = 0; i < CH; i++) {
            int idx = base + i;
            if (idx < N_NODES) sum += g_deg[idx];
        }
        sh[t] = sum;
        __syncthreads();
        for (int d = 1; d < CSR_THREADS; d <<= 1) {
            int v = (t >= d) ? sh[t - d] : 0;
            __syncthreads();
            sh[t] += v;
            __syncthreads();
        }
        int run = (t == 0) ? 0 : sh[t - 1];
        for (int i = 0; i < CH; i++) {
            int idx = base + i;
            if (idx < N_NODES) { g_off[idx] = run; run += g_deg[idx]; }
        }
        if (t == CSR_THREADS - 1) g_off[N_NODES] = run;
        __threadfence();
        __syncthreads();
        if (t == 0) atomicExch(&g_s2, 1);
    }
    if (t == 0) {
        while (*(volatile int*)&g_s2 == 0) { }
    }
    __syncthreads();

    // phase 3: scatter
    for (int e = gt; e < ETOT; e += STRIDE) {
        int d, s;
        if (e < E_EDGES) { d = dst[e]; s = src[e]; }
        else { d = e - E_EDGES; s = d; }
        int pos = g_off[d] + atomicAdd(&g_cursor[d], 1);
        g_csr_src[pos] = s;
    }
}

// ------------------------- 3x split-FP16 tensor GEMM + fused attention --------
// cp.async double-buffered, 128x128 tile, BK=32 halves, 2 CTAs/SM. (R11 kernel)
#define GBM 128
#define GBN 128
#define APH 40
#define BUF_H (128 * APH)
#define STAGE_H (4 * BUF_H)
#define GEMM_SMEM (2 * STAGE_H * 2)               // 81920 B

__global__ __launch_bounds__(256, 2) void k_gemm(const float* __restrict__ att_src,
                                                 const float* __restrict__ att_dst) {
    extern __shared__ __half smh[];

    int tid = threadIdx.x;
    int m0 = blockIdx.y * GBM;
    int n0 = blockIdx.x * GBN;
    int head = blockIdx.x;
    int warp = tid >> 5, lane = tid & 31;
    int g = lane >> 2, q = lane & 3;
    int wm = (warp >> 1) * 32;
    int wn = (warp & 1) * 64;

    float acc[2][8][4];
#pragma unroll
    for (int mi = 0; mi < 2; mi++)
#pragma unroll
        for (int ni = 0; ni < 8; ni++)
#pragma unroll
            for (int j = 0; j < 4; j++) acc[mi][ni][j] = 0.f;

    auto load_stage = [&](int buf, int st) {
        __half* Ah = smh + buf * STAGE_H;
        __half* Al = Ah + BUF_H;
        __half* Bh = Al + BUF_H;
        __half* Bl = Bh + BUF_H;
#pragma unroll
        for (int i = 0; i < 2; i++) {
            int idx = tid + i * 256;
            int r = idx >> 2, c8 = idx & 3;
            bool av = (m0 + r < N_NODES);
            cp_async16(&Ah[r * APH + c8 * 8], g_Xhi + (m0 + r) * NHID + st * 32 + c8 * 8, av);
            cp_async16(&Al[r * APH + c8 * 8], g_Xlo + (m0 + r) * NHID + st * 32 + c8 * 8, av);
            cp_async16(&Bh[r * APH + c8 * 8], g_Whi + (n0 + r) * NHID + st * 32 + c8 * 8, true);
            cp_async16(&Bl[r * APH + c8 * 8], g_Wlo + (n0 + r) * NHID + st * 32 + c8 * 8, true);
        }
    };

    load_stage(0, 0);
    CP_COMMIT();

    for (int st = 0; st < 4; st++) {
        if (st < 3) {
            load_stage((st + 1) & 1, st + 1);
            CP_COMMIT();
            CP_WAIT(1);
        } else {
            CP_WAIT(0);
        }
        __syncthreads();

        const __half* Ah = smh + (st & 1) * STAGE_H;
        const __half* Al = Ah + BUF_H;
        const __half* Bh = Al + BUF_H;
        const __half* Bl = Bh + BUF_H;

#pragma unroll
        for (int ks = 0; ks < 2; ks++) {
            int kb = ks * 16;
            unsigned ah[2][4], al[2][4];
#pragma unroll
            for (int mi = 0; mi < 2; mi++) {
                int r = wm + mi * 16 + g;
                ah[mi][0] = *(const unsigned*)&Ah[r * APH + kb + 2 * q];
                ah[mi][1] = *(const unsigned*)&Ah[(r + 8) * APH + kb + 2 * q];
                ah[mi][2] = *(const unsigned*)&Ah[r * APH + kb + 2 * q + 8];
                ah[mi][3] = *(const unsigned*)&Ah[(r + 8) * APH + kb + 2 * q + 8];
                al[mi][0] = *(const unsigned*)&Al[r * APH + kb + 2 * q];
                al[mi][1] = *(const unsigned*)&Al[(r + 8) * APH + kb + 2 * q];
                al[mi][2] = *(const unsigned*)&Al[r * APH + kb + 2 * q + 8];
                al[mi][3] = *(const unsigned*)&Al[(r + 8) * APH + kb + 2 * q + 8];
            }
#pragma unroll
            for (int ni = 0; ni < 8; ni++) {
                int c = wn + ni * 8 + g;
                unsigned bh[2], bl[2];
                bh[0] = *(const unsigned*)&Bh[c * APH + kb + 2 * q];
                bh[1] = *(const unsigned*)&Bh[c * APH + kb + 2 * q + 8];
                bl[0] = *(const unsigned*)&Bl[c * APH + kb + 2 * q];
                bl[1] = *(const unsigned*)&Bl[c * APH + kb + 2 * q + 8];
#pragma unroll
                for (int mi = 0; mi < 2; mi++) {
                    mma_f16(acc[mi][ni], ah[mi], bh);
                    mma_f16(acc[mi][ni], ah[mi], bl);
                    mma_f16(acc[mi][ni], al[mi], bh);
                }
            }
        }
        __syncthreads();
    }

    float* sAs = (float*)smh;
    float* sAd = ((float*)smh) + 256;

    float attS[16], attD[16];
#pragma unroll
    for (int ni = 0; ni < 8; ni++) {
        int c = n0 + wn + ni * 8 + 2 * q;
        attS[2 * ni] = att_src[c];     attS[2 * ni + 1] = att_src[c + 1];
        attD[2 * ni] = att_dst[c];     attD[2 * ni + 1] = att_dst[c + 1];
    }
#pragma unroll
    for (int mi = 0; mi < 2; mi++) {
        float s1a = 0.f, s2a = 0.f, s1b = 0.f, s2b = 0.f;
#pragma unroll
        for (int ni = 0; ni < 8; ni++) {
            s1a += acc[mi][ni][0] * attS[2 * ni] + acc[mi][ni][1] * attS[2 * ni + 1];
            s2a += acc[mi][ni][0] * attD[2 * ni] + acc[mi][ni][1] * attD[2 * ni + 1];
            s1b += acc[mi][ni][2] * attS[2 * ni] + acc[mi][ni][3] * attS[2 * ni + 1];
            s2b += acc[mi][ni][2] * attD[2 * ni] + acc[mi][ni][3] * attD[2 * ni + 1];
        }
#pragma unroll
        for (int o = 2; o; o >>= 1) {
            s1a += __shfl_down_sync(0xffffffffu, s1a, o, 4);
            s2a += __shfl_down_sync(0xffffffffu, s2a, o, 4);
            s1b += __shfl_down_sync(0xffffffffu, s1b, o, 4);
            s2b += __shfl_down_sync(0xffffffffu, s2b, o, 4);
        }
        if (q == 0) {
            int half = warp & 1;
            int rA = wm + mi * 16 + g;
            sAs[half * 128 + rA] = s1a;      sAd[half * 128 + rA] = s2a;
            sAs[half * 128 + rA + 8] = s1b;  sAd[half * 128 + rA + 8] = s2b;
        }
    }
    __syncthreads();
    if (tid < 128) {
        int r = m0 + tid;
        if (r < N_NODES) {
            g_as[r * HEADS + head] = sAs[tid] + sAs[128 + tid];
            g_ad[r * HEADS + head] = sAd[tid] + sAd[128 + tid];
        }
    }

#pragma unroll
    for (int mi = 0; mi < 2; mi++) {
        int r = m0 + wm + mi * 16 + g;
#pragma unroll
        for (int ni = 0; ni < 8; ni++) {
            int c = n0 + wn + ni * 8 + 2 * q;
            if (r < N_NODES)
                *((__half2*)(g_hh + r * HC + c)) = __floats2half2_rn(acc[mi][ni][0], acc[mi][ni][1]);
            if (r + 8 < N_NODES)
                *((__half2*)(g_hh + (r + 8) * HC + c)) = __floats2half2_rn(acc[mi][ni][2], acc[mi][ni][3]);
        }
    }
}

// ------------------------- fused softmax + aggregate + GraphCON update --------
// UNCHANGED from R11 (this round measures it in ncu slot 4).
#define ACH 64
__global__ __launch_bounds__(64) void k_aggregate(const float* __restrict__ bias,
                                                  float* __restrict__ out, int layer) {
    __shared__ int   s_src[ACH];
    __shared__ float s_ex[ACH * 4];
    __shared__ float4 s_den[2];

    int n = blockIdx.x;
    int t = threadIdx.x;
    int hd = t >> 4;
    int wid = t >> 5, lane = t & 31;
    int st = g_off[n], en = g_off[n + 1];
    float4 ad4 = ((const float4*)g_ad)[n];
    const uint4* h16 = (const uint4*)g_hh;

    float4 denp = make_float4(0.f, 0.f, 0.f, 0.f);
    float a0 = 0.f, a1 = 0.f, a2 = 0.f, a3 = 0.f;
    float a4 = 0.f, a5 = 0.f, a6 = 0.f, a7 = 0.f;

#define ACCUM(u, e) { \
    float2 p0 = __half22float2(*(const __half2*)&u.x); \
    float2 p1 = __half22float2(*(const __half2*)&u.y); \
    float2 p2 = __half22float2(*(const __half2*)&u.z); \
    float2 p3 = __half22float2(*(const __half2*)&u.w); \
    a0 += e * p0.x; a1 += e * p0.y; a2 += e * p1.x; a3 += e * p1.y; \
    a4 += e * p2.x; a5 += e * p2.y; a6 += e * p3.x; a7 += e * p3.y; }

    for (int c0 = st; c0 < en; c0 += ACH) {
        int cl = en - c0; if (cl > ACH) cl = ACH;
        if (t < cl) {
            int s = g_csr_src[c0 + t];
            float4 as4 = ((const float4*)g_as)[s];
            float e0 = as4.x + ad4.x, e1 = as4.y + ad4.y;
            float e2 = as4.z + ad4.z, e3 = as4.w + ad4.w;
            e0 = e0 > 0.f ? e0 : e0 * NEG_SLOPE;
            e1 = e1 > 0.f ? e1 : e1 * NEG_SLOPE;
            e2 = e2 > 0.f ? e2 : e2 * NEG_SLOPE;
            e3 = e3 > 0.f ? e3 : e3 * NEG_SLOPE;
            float x0 = __expf(e0), x1 = __expf(e1), x2 = __expf(e2), x3 = __expf(e3);
            s_src[t] = s;
            ((float4*)s_ex)[t] = make_float4(x0, x1, x2, x3);
            denp.x += x0; denp.y += x1; denp.z += x2; denp.w += x3;
        }
        __syncthreads();
        int j = 0;
        for (; j + 8 <= cl; j += 8) {
            int ss[8]; float ee[8]; uint4 uu[8];
#pragma unroll
            for (int u = 0; u < 8; u++) {
                ss[u] = s_src[j + u];
                ee[u] = s_ex[(j + u) * 4 + hd];
            }
#pragma unroll
            for (int u = 0; u < 8; u++) uu[u] = h16[ss[u] * 64 + t];
#pragma unroll
            for (int u = 0; u < 8; u++) ACCUM(uu[u], ee[u])
        }
        for (; j < cl; j++) {
            int s = s_src[j];
            float e = s_ex[j * 4 + hd];
            uint4 u = h16[s * 64 + t];
            ACCUM(u, e)
        }
        __syncthreads();
    }
#undef ACCUM

#pragma unroll
    for (int o = 16; o; o >>= 1) {
        denp.x += __shfl_xor_sync(0xffffffffu, denp.x, o);
        denp.y += __shfl_xor_sync(0xffffffffu, denp.y, o);
        denp.z += __shfl_xor_sync(0xffffffffu, denp.z, o);
        denp.w += __shfl_xor_sync(0xffffffffu, denp.w, o);
    }
    if (lane == 0) s_den[wid] = denp;
    __syncthreads();
    float4 d0 = s_den[0], d1 = s_den[1];
    float dens[4] = {d0.x + d1.x, d0.y + d1.y, d0.z + d1.z, d0.w + d1.w};
    float inv = 1.0f / dens[hd];

    const float4* b4p = (const float4*)(bias + 8 * t);
    float4 b0 = b4p[0], b1 = b4p[1];
    float g0 = a0 * inv + b0.x, g1 = a1 * inv + b0.y;
    float g2 = a2 * inv + b0.z, g3 = a3 * inv + b0.w;
    float g4 = a4 * inv + b1.x, g5 = a5 * inv + b1.y;
    float g6 = a6 * inv + b1.z, g7 = a7 * inv + b1.w;
    g0 = g0 > 0.f ? g0 : (expf(g0) - 1.f);
    g1 = g1 > 0.f ? g1 : (expf(g1) - 1.f);
    g2 = g2 > 0.f ? g2 : (expf(g2) - 1.f);
    g3 = g3 > 0.f ? g3 : (expf(g3) - 1.f);
    g4 = g4 > 0.f ? g4 : (expf(g4) - 1.f);
    g5 = g5 > 0.f ? g5 : (expf(g5) - 1.f);
    g6 = g6 > 0.f ? g6 : (expf(g6) - 1.f);
    g7 = g7 > 0.f ? g7 : (expf(g7) - 1.f);
    float aggA = 0.25f * (g0 + g1 + g2 + g3);
    float aggB = 0.25f * (g4 + g5 + g6 + g7);

    float2 xv = *((const float2*)(g_X + n * NHID + 2 * t));
    float2 yv = *((const float2*)(g_Y + n * NHID + 2 * t));
    float y2a = yv.x + DT * (aggA - ALPHA * yv.x - GAMMA * xv.x);
    float y2b = yv.y + DT * (aggB - ALPHA * yv.y - GAMMA * xv.y);
    float x2a = xv.x + DT * y2a;
    float x2b = xv.y + DT * y2b;
    *((float2*)(g_X + n * NHID + 2 * t)) = make_float2(x2a, x2b);
    *((float2*)(g_Y + n * NHID + 2 * t)) = make_float2(y2a, y2b);

    __half hA = __float2half_rn(x2a), hB = __float2half_rn(x2b);
    __half lA = __float2half_rn(x2a - __half2float(hA));
    __half lB = __float2half_rn(x2b - __half2float(hB));
    *((__half2*)(g_Xhi + n * NHID + 2 * t)) = __halves2half2(hA, hB);
    *((__half2*)(g_Xlo + n * NHID + 2 * t)) = __halves2half2(lA, lB);

    float* xo = out + XALL_OFF + n * LSTRIDE + (layer + 1) * NHID + 2 * t;
    float* yo = out + YALL_OFF + n * LSTRIDE + (layer + 1) * NHID + 2 * t;
    *((float2*)xo) = make_float2(x2a, x2b);
    *((float2*)yo) = make_float2(y2a, y2b);
}

// ------------------------- output projection ----------------------------------
__global__ void k_outproj(const float* __restrict__ Wr, const float* __restrict__ br,
                          float* __restrict__ out) {
    __shared__ float xs[NHID];
    int n = blockIdx.x;
    int t = threadIdx.x;
    xs[t] = g_X[n * NHID + t];
    __syncthreads();
    if (t < NCLASS) {
        const float* w = Wr + t * NHID;
        float acc = 0.f;
#pragma unroll 8
        for (int k = 0; k < NHID; k++) acc += xs[k] * w[k];
        out[OUT_OFF + n * NCLASS + t] = acc + br[t];
    }
}

// ------------------------- launch ---------------------------------------------
extern "C" void kernel_launch(void* const* d_in, const int* in_sizes, int n_in,
                              void* d_out, int out_size) {
    const float* x       = (const float*)d_in[0];
    const int*   src     = (const int*)d_in[1];
    const int*   dst     = (const int*)d_in[2];
    const float* W       = (const float*)d_in[3];
    const float* att_src = (const float*)d_in[4];
    const float* att_dst = (const float*)d_in[5];
    const float* bias    = (const float*)d_in[6];
    const float* Wr      = (const float*)d_in[7];
    const float* br      = (const float*)d_in[8];
    float* out = (float*)d_out;

    cudaFuncSetAttribute(k_gemm, cudaFuncAttributeMaxDynamicSharedMemorySize, GEMM_SMEM);

    dim3 ggrid(HC / GBN, (N_NODES + GBM - 1) / GBM);   // (4, 157)

    // slot-4 = k_aggregate (the ncu-profiled launch)
    k_setup<<<N_NODES, NHID>>>(x, W, out);                   // 1
    k_csr<<<CSR_BLOCKS, CSR_THREADS>>>(src, dst);            // 2
    k_gemm<<<ggrid, 256, GEMM_SMEM>>>(att_src, att_dst);     // 3 (layer 0)
    k_aggregate<<<N_NODES, 64>>>(bias, out, 0);              // 4 (layer 0)  <- profiled

    for (int l = 1; l < NLAYERS; l++) {
        k_gemm<<<ggrid, 256, GEMM_SMEM>>>(att_src, att_dst);
        k_aggregate<<<N_NODES, 64>>>(bias, out, l);
    }
    k_outproj<<<N_NODES, 128>>>(Wr, br, out);
}

// round 13
// speedup vs baseline: 1.0424x; 1.0144x over previous
#include <cuda_runtime.h>
#include <cuda_fp16.h>
#include <math.h>

#define N_NODES 20000
#define NHID 128
#define HEADS 4
#define HC (HEADS * NHID)          // 512
#define E_EDGES 320000
#define ETOT (E_EDGES + N_NODES)   // 340000
#define NLAYERS 4
#define NCLASS 40
#define NEG_SLOPE 0.2f
#define DT 1.0f
#define ALPHA 1.0f
#define GAMMA 1.0f

// d_out layout: [out (N*NCLASS)] [X_all (N*(L+1)*C)] [Y_all (N*(L+1)*C)]
#define OUT_OFF   0
#define XALL_OFF  (N_NODES * NCLASS)
#define YALL_OFF  (XALL_OFF + N_NODES * (NLAYERS + 1) * NHID)
#define LSTRIDE   ((NLAYERS + 1) * NHID)

// ------------------------- device scratch (no allocs allowed) ----------------
__device__ __half g_hh[N_NODES * HC];        // fp16 messages
__device__ float  g_X[N_NODES * NHID];
__device__ float  g_Y[N_NODES * NHID];
__device__ __half g_Xhi[N_NODES * NHID];     // double-fp16 split X (GEMM A)
__device__ __half g_Xlo[N_NODES * NHID];
__device__ __half g_Whi[HC * NHID];          // split W, TRANSPOSED [n][k]
__device__ __half g_Wlo[HC * NHID];
__device__ float  g_as[N_NODES * HEADS];
__device__ float  g_ad[N_NODES * HEADS];
__device__ int    g_deg[N_NODES];
__device__ int    g_cursor[N_NODES];
__device__ int    g_off[N_NODES + 1];
__device__ int    g_csr_src[ETOT];
__device__ int    g_s1;                      // grid-sync flags for k_csr
__device__ int    g_s2;

__device__ __forceinline__ void mma_f16(float* c, const unsigned* a, const unsigned* b) {
    asm volatile(
        "mma.sync.aligned.m16n8k16.row.col.f32.f16.f16.f32 "
        "{%0,%1,%2,%3}, {%4,%5,%6,%7}, {%8,%9}, {%0,%1,%2,%3};\n"
        : "+f"(c[0]), "+f"(c[1]), "+f"(c[2]), "+f"(c[3])
        : "r"(a[0]), "r"(a[1]), "r"(a[2]), "r"(a[3]), "r"(b[0]), "r"(b[1]));
}

#define LDSM4(r0, r1, r2, r3, addr) \
    asm volatile("ldmatrix.sync.aligned.m8n8.x4.shared.b16 {%0,%1,%2,%3}, [%4];" \
                 : "=r"(r0), "=r"(r1), "=r"(r2), "=r"(r3) : "r"(addr))

__device__ __forceinline__ void cp_async16(void* smem_dst, const void* gmem_src, bool valid) {
    unsigned sm = (unsigned)__cvta_generic_to_shared(smem_dst);
    int sz = valid ? 16 : 0;
    asm volatile("cp.async.cg.shared.global [%0], [%1], 16, %2;\n"
                 :: "r"(sm), "l"(gmem_src), "r"(sz));
}
#define CP_COMMIT() asm volatile("cp.async.commit_group;\n" ::: "memory")
#define CP_WAIT(n)  asm volatile("cp.async.wait_group %0;\n" :: "n"(n) : "memory")

// ------------------------- setup kernels -------------------------------------
// split W (fp16 hi/lo, transposed to [n][k]). 65536 threads.
__global__ void k_splitW(const float* __restrict__ W) {
    int i = blockIdx.x * blockDim.x + threadIdx.x;
    float w = W[i];
    __half hi = __float2half_rn(w);
    g_Whi[(i & 511) * NHID + (i >> 9)] = hi;
    g_Wlo[(i & 511) * NHID + (i >> 9)] = __float2half_rn(w - __half2float(hi));
}

// init state + zero CSR scratch + layer-0 output slices
__global__ void k_setup(const float* __restrict__ x, float* __restrict__ out) {
    int n = blockIdx.x;
    int t = threadIdx.x;
    float v = x[n * NHID + t];
    g_X[n * NHID + t] = v;
    g_Y[n * NHID + t] = v;
    __half hi = __float2half_rn(v);
    g_Xhi[n * NHID + t] = hi;
    g_Xlo[n * NHID + t] = __float2half_rn(v - __half2float(hi));
    out[XALL_OFF + n * LSTRIDE + t] = v;
    out[YALL_OFF + n * LSTRIDE + t] = v;
    if (t == 0) { g_deg[n] = 0; g_cursor[n] = 0; }
    if (n == 0 && t == 0) { g_s1 = 0; g_s2 = 0; }
}

// ------------------------- CSR build in ONE kernel (all-resident grid) --------
#define CSR_BLOCKS 148
#define CSR_THREADS 256
__global__ __launch_bounds__(CSR_THREADS) void k_csr(const int* __restrict__ src,
                                                     const int* __restrict__ dst) {
    int t = threadIdx.x;
    int gt = blockIdx.x * CSR_THREADS + t;
    const int STRIDE = CSR_BLOCKS * CSR_THREADS;

    for (int e = gt; e < ETOT; e += STRIDE) {
        int d = (e < E_EDGES) ? dst[e] : (e - E_EDGES);
        atomicAdd(&g_deg[d], 1);
    }
    __threadfence();
    __syncthreads();
    if (t == 0) {
        atomicAdd(&g_s1, 1);
        while (*(volatile int*)&g_s1 < CSR_BLOCKS) { }
    }
    __syncthreads();

    if (blockIdx.x == 0) {
        __shared__ int sh[CSR_THREADS];
        const int CH = (N_NODES + CSR_THREADS - 1) / CSR_THREADS;  // 79
        int base = t * CH;
        int sum = 0;
        for (int i = 0; i < CH; i++) {
            int idx = base + i;
            if (idx < N_NODES) sum += g_deg[idx];
        }
        sh[t] = sum;
        __syncthreads();
        for (int d = 1; d < CSR_THREADS; d <<= 1) {
            int v = (t >= d) ? sh[t - d] : 0;
            __syncthreads();
            sh[t] += v;
            __syncthreads();
        }
        int run = (t == 0) ? 0 : sh[t - 1];
        for (int i = 0; i < CH; i++) {
            int idx = base + i;
            if (idx < N_NODES) { g_off[idx] = run; run += g_deg[idx]; }
        }
        if (t == CSR_THREADS - 1) g_off[N_NODES] = run;
        __threadfence();
        __syncthreads();
        if (t == 0) atomicExch(&g_s2, 1);
    }
    if (t == 0) {
        while (*(volatile int*)&g_s2 == 0) { }
    }
    __syncthreads();

    for (int e = gt; e < ETOT; e += STRIDE) {
        int d, s;
        if (e < E_EDGES) { d = dst[e]; s = src[e]; }
        else { d = e - E_EDGES; s = d; }
        int pos = g_off[d] + atomicAdd(&g_cursor[d], 1);
        g_csr_src[pos] = s;
    }
}

// ------------------------- 3x split-FP16 tensor GEMM + fused attention --------
// cp.async double-buffered, 128x128 tile, BK=32 halves, 2 CTAs/SM.
// Fragment loads via ldmatrix.x4: 12 LDSM per k-step vs 96 scalar LDS before.
#define GBM 128
#define GBN 128
#define APH 40
#define BUF_H (128 * APH)
#define STAGE_H (4 * BUF_H)
#define GEMM_SMEM (2 * STAGE_H * 2)               // 81920 B

__global__ __launch_bounds__(256, 2) void k_gemm(const float* __restrict__ att_src,
                                                 const float* __restrict__ att_dst) {
    extern __shared__ __half smh[];

    int tid = threadIdx.x;
    int m0 = blockIdx.y * GBM;
    int n0 = blockIdx.x * GBN;
    int head = blockIdx.x;
    int warp = tid >> 5, lane = tid & 31;
    int g = lane >> 2, q = lane & 3;
    int wm = (warp >> 1) * 32;
    int wn = (warp & 1) * 64;

    float acc[2][8][4];
#pragma unroll
    for (int mi = 0; mi < 2; mi++)
#pragma unroll
        for (int ni = 0; ni < 8; ni++)
#pragma unroll
            for (int j = 0; j < 4; j++) acc[mi][ni][j] = 0.f;

    auto load_stage = [&](int buf, int st) {
        __half* Ah = smh + buf * STAGE_H;
        __half* Al = Ah + BUF_H;
        __half* Bh = Al + BUF_H;
        __half* Bl = Bh + BUF_H;
#pragma unroll
        for (int i = 0; i < 2; i++) {
            int idx = tid + i * 256;
            int r = idx >> 2, c8 = idx & 3;
            bool av = (m0 + r < N_NODES);
            cp_async16(&Ah[r * APH + c8 * 8], g_Xhi + (m0 + r) * NHID + st * 32 + c8 * 8, av);
            cp_async16(&Al[r * APH + c8 * 8], g_Xlo + (m0 + r) * NHID + st * 32 + c8 * 8, av);
            cp_async16(&Bh[r * APH + c8 * 8], g_Whi + (n0 + r) * NHID + st * 32 + c8 * 8, true);
            cp_async16(&Bl[r * APH + c8 * 8], g_Wlo + (n0 + r) * NHID + st * 32 + c8 * 8, true);
        }
    };

    // per-thread ldmatrix addresses (byte offsets within a stage)
    unsigned smbase = (unsigned)__cvta_generic_to_shared(smh);
    // A: row = wm + (lane&15) (+ mi*16), kcol = (lane>>4)*8 (+ kb)
    unsigned aoff = ((wm + (lane & 15)) * APH + ((lane >> 4) << 3)) * 2;
    // B: row = wn + (lane&7) + ((lane>>4)<<3) (+ p*16), kcol = ((lane>>3)&1)*8 (+ kb)
    unsigned boff = ((wn + (lane & 7) + ((lane >> 4) << 3)) * APH + (((lane >> 3) & 1) << 3)) * 2;

    load_stage(0, 0);
    CP_COMMIT();

    for (int st = 0; st < 4; st++) {
        if (st < 3) {
            load_stage((st + 1) & 1, st + 1);
            CP_COMMIT();
            CP_WAIT(1);
        } else {
            CP_WAIT(0);
        }
        __syncthreads();

        unsigned stageB = smbase + (unsigned)((st & 1) * STAGE_H * 2);
        unsigned aHi = stageB + aoff;
        unsigned aLo = aHi + BUF_H * 2;
        unsigned bHi = stageB + 2 * BUF_H * 2 + boff;
        unsigned bLo = bHi + BUF_H * 2;

#pragma unroll
        for (int ks = 0; ks < 2; ks++) {
            unsigned kbB = ks * 32;                    // 16 halves = 32 bytes
            unsigned ah[2][4], al[2][4];
#pragma unroll
            for (int mi = 0; mi < 2; mi++) {
                LDSM4(ah[mi][0], ah[mi][1], ah[mi][2], ah[mi][3],
                      aHi + mi * (16 * APH * 2) + kbB);
                LDSM4(al[mi][0], al[mi][1], al[mi][2], al[mi][3],
                      aLo + mi * (16 * APH * 2) + kbB);
            }
#pragma unroll
            for (int p = 0; p < 4; p++) {              // ni pairs (2p, 2p+1)
                unsigned bh[4], bl[4];
                LDSM4(bh[0], bh[1], bh[2], bh[3], bHi + p * (16 * APH * 2) + kbB);
                LDSM4(bl[0], bl[1], bl[2], bl[3], bLo + p * (16 * APH * 2) + kbB);
#pragma unroll
                for (int mi = 0; mi < 2; mi++) {
                    mma_f16(acc[mi][2 * p],     ah[mi], bh);       // hi*hi (b0,b1)
                    mma_f16(acc[mi][2 * p],     ah[mi], bl);       // hi*lo
                    mma_f16(acc[mi][2 * p],     al[mi], bh);       // lo*hi
                    mma_f16(acc[mi][2 * p + 1], ah[mi], bh + 2);   // tiles 2,3 = ni odd
                    mma_f16(acc[mi][2 * p + 1], ah[mi], bl + 2);
                    mma_f16(acc[mi][2 * p + 1], al[mi], bh + 2);
                }
            }
        }
        __syncthreads();
    }

    float* sAs = (float*)smh;
    float* sAd = ((float*)smh) + 256;

    float attS[16], attD[16];
#pragma unroll
    for (int ni = 0; ni < 8; ni++) {
        int c = n0 + wn + ni * 8 + 2 * q;
        attS[2 * ni] = att_src[c];     attS[2 * ni + 1] = att_src[c + 1];
        attD[2 * ni] = att_dst[c];     attD[2 * ni + 1] = att_dst[c + 1];
    }
#pragma unroll
    for (int mi = 0; mi < 2; mi++) {
        float s1a = 0.f, s2a = 0.f, s1b = 0.f, s2b = 0.f;
#pragma unroll
        for (int ni = 0; ni < 8; ni++) {
            s1a += acc[mi][ni][0] * attS[2 * ni] + acc[mi][ni][1] * attS[2 * ni + 1];
            s2a += acc[mi][ni][0] * attD[2 * ni] + acc[mi][ni][1] * attD[2 * ni + 1];
            s1b += acc[mi][ni][2] * attS[2 * ni] + acc[mi][ni][3] * attS[2 * ni + 1];
            s2b += acc[mi][ni][2] * attD[2 * ni] + acc[mi][ni][3] * attD[2 * ni + 1];
        }
#pragma unroll
        for (int o = 2; o; o >>= 1) {
            s1a += __shfl_down_sync(0xffffffffu, s1a, o, 4);
            s2a += __shfl_down_sync(0xffffffffu, s2a, o, 4);
            s1b += __shfl_down_sync(0xffffffffu, s1b, o, 4);
            s2b += __shfl_down_sync(0xffffffffu, s2b, o, 4);
        }
        if (q == 0) {
            int half = warp & 1;
            int rA = wm + mi * 16 + g;
            sAs[half * 128 + rA] = s1a;      sAd[half * 128 + rA] = s2a;
            sAs[half * 128 + rA + 8] = s1b;  sAd[half * 128 + rA + 8] = s2b;
        }
    }
    __syncthreads();
    if (tid < 128) {
        int r = m0 + tid;
        if (r < N_NODES) {
            g_as[r * HEADS + head] = sAs[tid] + sAs[128 + tid];
            g_ad[r * HEADS + head] = sAd[tid] + sAd[128 + tid];
        }
    }

#pragma unroll
    for (int mi = 0; mi < 2; mi++) {
        int r = m0 + wm + mi * 16 + g;
#pragma unroll
        for (int ni = 0; ni < 8; ni++) {
            int c = n0 + wn + ni * 8 + 2 * q;
            if (r < N_NODES)
                *((__half2*)(g_hh + r * HC + c)) = __floats2half2_rn(acc[mi][ni][0], acc[mi][ni][1]);
            if (r + 8 < N_NODES)
                *((__half2*)(g_hh + (r + 8) * HC + c)) = __floats2half2_rn(acc[mi][ni][2], acc[mi][ni][3]);
        }
    }
}

// ------------------------- fused softmax + aggregate + GraphCON update --------
#define ACH 64
__global__ __launch_bounds__(64) void k_aggregate(const float* __restrict__ bias,
                                                  float* __restrict__ out, int layer) {
    __shared__ int   s_src[ACH];
    __shared__ float s_ex[ACH * 4];
    __shared__ float4 s_den[2];

    int n = blockIdx.x;
    int t = threadIdx.x;
    int hd = t >> 4;
    int wid = t >> 5, lane = t & 31;
    int st = g_off[n], en = g_off[n + 1];
    float4 ad4 = ((const float4*)g_ad)[n];
    const uint4* h16 = (const uint4*)g_hh;

    float4 denp = make_float4(0.f, 0.f, 0.f, 0.f);
    float a0 = 0.f, a1 = 0.f, a2 = 0.f, a3 = 0.f;
    float a4 = 0.f, a5 = 0.f, a6 = 0.f, a7 = 0.f;

#define ACCUM(u, e) { \
    float2 p0 = __half22float2(*(const __half2*)&u.x); \
    float2 p1 = __half22float2(*(const __half2*)&u.y); \
    float2 p2 = __half22float2(*(const __half2*)&u.z); \
    float2 p3 = __half22float2(*(const __half2*)&u.w); \
    a0 += e * p0.x; a1 += e * p0.y; a2 += e * p1.x; a3 += e * p1.y; \
    a4 += e * p2.x; a5 += e * p2.y; a6 += e * p3.x; a7 += e * p3.y; }

    for (int c0 = st; c0 < en; c0 += ACH) {
        int cl = en - c0; if (cl > ACH) cl = ACH;
        if (t < cl) {
            int s = g_csr_src[c0 + t];
            float4 as4 = ((const float4*)g_as)[s];
            float e0 = as4.x + ad4.x, e1 = as4.y + ad4.y;
            float e2 = as4.z + ad4.z, e3 = as4.w + ad4.w;
            e0 = e0 > 0.f ? e0 : e0 * NEG_SLOPE;
            e1 = e1 > 0.f ? e1 : e1 * NEG_SLOPE;
            e2 = e2 > 0.f ? e2 : e2 * NEG_SLOPE;
            e3 = e3 > 0.f ? e3 : e3 * NEG_SLOPE;
            float x0 = __expf(e0), x1 = __expf(e1), x2 = __expf(e2), x3 = __expf(e3);
            s_src[t] = s;
            ((float4*)s_ex)[t] = make_float4(x0, x1, x2, x3);
            denp.x += x0; denp.y += x1; denp.z += x2; denp.w += x3;
        }
        __syncthreads();
        int j = 0;
        for (; j + 8 <= cl; j += 8) {
            int ss[8]; float ee[8]; uint4 uu[8];
#pragma unroll
            for (int u = 0; u < 8; u++) {
                ss[u] = s_src[j + u];
                ee[u] = s_ex[(j + u) * 4 + hd];
            }
#pragma unroll
            for (int u = 0; u < 8; u++) uu[u] = h16[ss[u] * 64 + t];
#pragma unroll
            for (int u = 0; u < 8; u++) ACCUM(uu[u], ee[u])
        }
        for (; j < cl; j++) {
            int s = s_src[j];
            float e = s_ex[j * 4 + hd];
            uint4 u = h16[s * 64 + t];
            ACCUM(u, e)
        }
        __syncthreads();
    }
#undef ACCUM

#pragma unroll
    for (int o = 16; o; o >>= 1) {
        denp.x += __shfl_xor_sync(0xffffffffu, denp.x, o);
        denp.y += __shfl_xor_sync(0xffffffffu, denp.y, o);
        denp.z += __shfl_xor_sync(0xffffffffu, denp.z, o);
        denp.w += __shfl_xor_sync(0xffffffffu, denp.w, o);
    }
    if (lane == 0) s_den[wid] = denp;
    __syncthreads();
    float4 d0 = s_den[0], d1 = s_den[1];
    float dens[4] = {d0.x + d1.x, d0.y + d1.y, d0.z + d1.z, d0.w + d1.w};
    float inv = 1.0f / dens[hd];

    const float4* b4p = (const float4*)(bias + 8 * t);
    float4 b0 = b4p[0], b1 = b4p[1];
    float g0 = a0 * inv + b0.x, g1 = a1 * inv + b0.y;
    float g2 = a2 * inv + b0.z, g3 = a3 * inv + b0.w;
    float g4 = a4 * inv + b1.x, g5 = a5 * inv + b1.y;
    float g6 = a6 * inv + b1.z, g7 = a7 * inv + b1.w;
    g0 = g0 > 0.f ? g0 : (__expf(g0) - 1.f);
    g1 = g1 > 0.f ? g1 : (__expf(g1) - 1.f);
    g2 = g2 > 0.f ? g2 : (__expf(g2) - 1.f);
    g3 = g3 > 0.f ? g3 : (__expf(g3) - 1.f);
    g4 = g4 > 0.f ? g4 : (__expf(g4) - 1.f);
    g5 = g5 > 0.f ? g5 : (__expf(g5) - 1.f);
    g6 = g6 > 0.f ? g6 : (__expf(g6) - 1.f);
    g7 = g7 > 0.f ? g7 : (__expf(g7) - 1.f);
    float aggA = 0.25f * (g0 + g1 + g2 + g3);
    float aggB = 0.25f * (g4 + g5 + g6 + g7);

    float2 xv = *((const float2*)(g_X + n * NHID + 2 * t));
    float2 yv = *((const float2*)(g_Y + n * NHID + 2 * t));
    float y2a = yv.x + DT * (aggA - ALPHA * yv.x - GAMMA * xv.x);
    float y2b = yv.y + DT * (aggB - ALPHA * yv.y - GAMMA * xv.y);
    float x2a = xv.x + DT * y2a;
    float x2b = xv.y + DT * y2b;
    *((float2*)(g_X + n * NHID + 2 * t)) = make_float2(x2a, x2b);
    *((float2*)(g_Y + n * NHID + 2 * t)) = make_float2(y2a, y2b);

    __half hA = __float2half_rn(x2a), hB = __float2half_rn(x2b);
    __half lA = __float2half_rn(x2a - __half2float(hA));
    __half lB = __float2half_rn(x2b - __half2float(hB));
    *((__half2*)(g_Xhi + n * NHID + 2 * t)) = __halves2half2(hA, hB);
    *((__half2*)(g_Xlo + n * NHID + 2 * t)) = __halves2half2(lA, lB);

    float* xo = out + XALL_OFF + n * LSTRIDE + (layer + 1) * NHID + 2 * t;
    float* yo = out + YALL_OFF + n * LSTRIDE + (layer + 1) * NHID + 2 * t;
    *((float2*)xo) = make_float2(x2a, x2b);
    *((float2*)yo) = make_float2(y2a, y2b);
}

// ------------------------- output projection ----------------------------------
__global__ void k_outproj(const float* __restrict__ Wr, const float* __restrict__ br,
                          float* __restrict__ out) {
    __shared__ float xs[NHID];
    int n = blockIdx.x;
    int t = threadIdx.x;
    xs[t] = g_X[n * NHID + t];
    __syncthreads();
    if (t < NCLASS) {
        const float* w = Wr + t * NHID;
        float acc = 0.f;
#pragma unroll 8
        for (int k = 0; k < NHID; k++) acc += xs[k] * w[k];
        out[OUT_OFF + n * NCLASS + t] = acc + br[t];
    }
}

// ------------------------- launch ---------------------------------------------
extern "C" void kernel_launch(void* const* d_in, const int* in_sizes, int n_in,
                              void* d_out, int out_size) {
    const float* x       = (const float*)d_in[0];
    const int*   src     = (const int*)d_in[1];
    const int*   dst     = (const int*)d_in[2];
    const float* W       = (const float*)d_in[3];
    const float* att_src = (const float*)d_in[4];
    const float* att_dst = (const float*)d_in[5];
    const float* bias    = (const float*)d_in[6];
    const float* Wr      = (const float*)d_in[7];
    const float* br      = (const float*)d_in[8];
    float* out = (float*)d_out;

    cudaFuncSetAttribute(k_gemm, cudaFuncAttributeMaxDynamicSharedMemorySize, GEMM_SMEM);

    dim3 ggrid(HC / GBN, (N_NODES + GBM - 1) / GBM);   // (4, 157)

    // k_gemm back in the profiled 4th slot
    k_splitW<<<(NHID * HC) / 256, 256>>>(W);                 // 1
    k_setup<<<N_NODES, NHID>>>(x, out);                      // 2
    k_csr<<<CSR_BLOCKS, CSR_THREADS>>>(src, dst);            // 3
    k_gemm<<<ggrid, 256, GEMM_SMEM>>>(att_src, att_dst);     // 4 (layer 0) <- profiled
    k_aggregate<<<N_NODES, 64>>>(bias, out, 0);              // 5 (layer 0)

    for (int l = 1; l < NLAYERS; l++) {
        k_gemm<<<ggrid, 256, GEMM_SMEM>>>(att_src, att_dst);
        k_aggregate<<<N_NODES, 64>>>(bias, out, l);
    }
    k_outproj<<<N_NODES, 128>>>(Wr, br, out);
}

// round 15
// speedup vs baseline: 1.0558x; 1.0129x over previous
#include <cuda_runtime.h>
#include <cuda_fp16.h>
#include <math.h>

#define N_NODES 20000
#define NHID 128
#define HEADS 4
#define HC (HEADS * NHID)          // 512
#define E_EDGES 320000
#define ETOT (E_EDGES + N_NODES)   // 340000
#define NLAYERS 4
#define NCLASS 40
#define NEG_SLOPE 0.2f
#define DT 1.0f
#define ALPHA 1.0f
#define GAMMA 1.0f

// d_out layout: [out (N*NCLASS)] [X_all (N*(L+1)*C)] [Y_all (N*(L+1)*C)]
#define OUT_OFF   0
#define XALL_OFF  (N_NODES * NCLASS)
#define YALL_OFF  (XALL_OFF + N_NODES * (NLAYERS + 1) * NHID)
#define LSTRIDE   ((NLAYERS + 1) * NHID)

// ------------------------- device scratch (no allocs allowed) ----------------
__device__ __half g_hh[N_NODES * HC];        // fp16 messages
__device__ float  g_X[N_NODES * NHID];
__device__ float  g_Y[N_NODES * NHID];
__device__ __half g_Xhi[N_NODES * NHID];     // double-fp16 split X (GEMM A)
__device__ __half g_Xlo[N_NODES * NHID];
__device__ __half g_Whi[HC * NHID];          // split W, TRANSPOSED [n][k]
__device__ __half g_Wlo[HC * NHID];
__device__ float  g_as[N_NODES * HEADS];
__device__ float  g_ad[N_NODES * HEADS];
__device__ int    g_deg[N_NODES];
__device__ int    g_cursor[N_NODES];
__device__ int    g_off[N_NODES + 1];
__device__ int    g_csr_src[ETOT];
__device__ int    g_s1;                      // grid-sync flags for k_csr
__device__ int    g_s2;

__device__ __forceinline__ void mma_f16(float* c, const unsigned* a, const unsigned* b) {
    asm volatile(
        "mma.sync.aligned.m16n8k16.row.col.f32.f16.f16.f32 "
        "{%0,%1,%2,%3}, {%4,%5,%6,%7}, {%8,%9}, {%0,%1,%2,%3};\n"
        : "+f"(c[0]), "+f"(c[1]), "+f"(c[2]), "+f"(c[3])
        : "r"(a[0]), "r"(a[1]), "r"(a[2]), "r"(a[3]), "r"(b[0]), "r"(b[1]));
}

#define LDSM4(r0, r1, r2, r3, addr) \
    asm volatile("ldmatrix.sync.aligned.m8n8.x4.shared.b16 {%0,%1,%2,%3}, [%4];" \
                 : "=r"(r0), "=r"(r1), "=r"(r2), "=r"(r3) : "r"(addr))

__device__ __forceinline__ void cp_async16(void* smem_dst, const void* gmem_src, bool valid) {
    unsigned sm = (unsigned)__cvta_generic_to_shared(smem_dst);
    int sz = valid ? 16 : 0;
    asm volatile("cp.async.cg.shared.global [%0], [%1], 16, %2;\n"
                 :: "r"(sm), "l"(gmem_src), "r"(sz));
}
#define CP_COMMIT() asm volatile("cp.async.commit_group;\n" ::: "memory")
#define CP_WAIT(n)  asm volatile("cp.async.wait_group %0;\n" :: "n"(n) : "memory")

// ------------------------- setup kernels -------------------------------------
__global__ void k_splitW(const float* __restrict__ W) {
    int i = blockIdx.x * blockDim.x + threadIdx.x;
    float w = W[i];
    __half hi = __float2half_rn(w);
    g_Whi[(i & 511) * NHID + (i >> 9)] = hi;
    g_Wlo[(i & 511) * NHID + (i >> 9)] = __float2half_rn(w - __half2float(hi));
}

__global__ void k_setup(const float* __restrict__ x, float* __restrict__ out) {
    int n = blockIdx.x;
    int t = threadIdx.x;
    float v = x[n * NHID + t];
    g_X[n * NHID + t] = v;
    g_Y[n * NHID + t] = v;
    __half hi = __float2half_rn(v);
    g_Xhi[n * NHID + t] = hi;
    g_Xlo[n * NHID + t] = __float2half_rn(v - __half2float(hi));
    out[XALL_OFF + n * LSTRIDE + t] = v;
    out[YALL_OFF + n * LSTRIDE + t] = v;
    if (t == 0) { g_deg[n] = 0; g_cursor[n] = 0; }
    if (n == 0 && t == 0) { g_s1 = 0; g_s2 = 0; }
}

// ------------------------- CSR build in ONE kernel (all-resident grid) --------
#define CSR_BLOCKS 148
#define CSR_THREADS 256
__global__ __launch_bounds__(CSR_THREADS) void k_csr(const int* __restrict__ src,
                                                     const int* __restrict__ dst) {
    int t = threadIdx.x;
    int gt = blockIdx.x * CSR_THREADS + t;
    const int STRIDE = CSR_BLOCKS * CSR_THREADS;

    for (int e = gt; e < ETOT; e += STRIDE) {
        int d = (e < E_EDGES) ? dst[e] : (e - E_EDGES);
        atomicAdd(&g_deg[d], 1);
    }
    __threadfence();
    __syncthreads();
    if (t == 0) {
        atomicAdd(&g_s1, 1);
        while (*(volatile int*)&g_s1 < CSR_BLOCKS) { }
    }
    __syncthreads();

    if (blockIdx.x == 0) {
        __shared__ int sh[CSR_THREADS];
        const int CH = (N_NODES + CSR_THREADS - 1) / CSR_THREADS;  // 79
        int base = t * CH;
        int sum = 0;
        for (int i = 0; i < CH; i++) {
            int idx = base + i;
            if (idx < N_NODES) sum += g_deg[idx];
        }
        sh[t] = sum;
        __syncthreads();
        for (int d = 1; d < CSR_THREADS; d <<= 1) {
            int v = (t >= d) ? sh[t - d] : 0;
            __syncthreads();
            sh[t] += v;
            __syncthreads();
        }
        int run = (t == 0) ? 0 : sh[t - 1];
        for (int i = 0; i < CH; i++) {
            int idx = base + i;
            if (idx < N_NODES) { g_off[idx] = run; run += g_deg[idx]; }
        }
        if (t == CSR_THREADS - 1) g_off[N_NODES] = run;
        __threadfence();
        __syncthreads();
        if (t == 0) atomicExch(&g_s2, 1);
    }
    if (t == 0) {
        while (*(volatile int*)&g_s2 == 0) { }
    }
    __syncthreads();

    for (int e = gt; e < ETOT; e += STRIDE) {
        int d, s;
        if (e < E_EDGES) { d = dst[e]; s = src[e]; }
        else { d = e - E_EDGES; s = d; }
        int pos = g_off[d] + atomicAdd(&g_cursor[d], 1);
        g_csr_src[pos] = s;
    }
}

// ------------------------- 3x split-FP16 tensor GEMM + fused attention --------
// B (=W) hi/lo SMEM-RESIDENT (full K, pitch 136 halves, conflict-free ldmatrix);
// only A streams through a 2-stage cp.async pipeline (10 KB/stage vs 40 before).
// smem 110.6 KB/CTA -> 2 CTAs/SM.
#define GBM 128
#define GBN 128
#define APH 40                       // A pitch (halves)
#define BPH 136                      // B pitch (halves)
#define A_BUF_H (128 * APH)          // 5120 halves per A buffer
#define A_STAGE_H (2 * A_BUF_H)      // hi+lo per stage = 10240 halves
#define B_BUF_H (128 * BPH)          // 17408 halves per B buffer
#define B_BASE_H (2 * A_STAGE_H)     // B starts after 2 A stages (20480 halves)
#define GEMM_SMEM ((B_BASE_H + 2 * B_BUF_H) * 2)   // 110592 B

__global__ __launch_bounds__(256, 2) void k_gemm(const float* __restrict__ att_src,
                                                 const float* __restrict__ att_dst) {
    extern __shared__ __half smh[];

    int tid = threadIdx.x;
    int m0 = blockIdx.y * GBM;
    int n0 = blockIdx.x * GBN;
    int head = blockIdx.x;
    int warp = tid >> 5, lane = tid & 31;
    int g = lane >> 2, q = lane & 3;
    int wm = (warp >> 1) * 32;
    int wn = (warp & 1) * 64;

    float acc[2][8][4];
#pragma unroll
    for (int mi = 0; mi < 2; mi++)
#pragma unroll
        for (int ni = 0; ni < 8; ni++)
#pragma unroll
            for (int j = 0; j < 4; j++) acc[mi][ni][j] = 0.f;

    __half* Bh = smh + B_BASE_H;
    __half* Bl = Bh + B_BUF_H;

    // B load: full W tile, once. 2048 16B-chunks per precision.
    auto load_B = [&]() {
#pragma unroll
        for (int i = 0; i < 8; i++) {
            int idx = tid + i * 256;            // 0..2047
            int r = idx >> 4, c8 = idx & 15;
            cp_async16(&Bh[r * BPH + c8 * 8], g_Whi + (n0 + r) * NHID + c8 * 8, true);
            cp_async16(&Bl[r * BPH + c8 * 8], g_Wlo + (n0 + r) * NHID + c8 * 8, true);
        }
    };
    // A stage load: 512 chunks per precision.
    auto load_A = [&](int buf, int st) {
        __half* Ah = smh + buf * A_STAGE_H;
        __half* Al = Ah + A_BUF_H;
#pragma unroll
        for (int i = 0; i < 2; i++) {
            int idx = tid + i * 256;            // 0..511
            int r = idx >> 2, c8 = idx & 3;
            bool av = (m0 + r < N_NODES);
            cp_async16(&Ah[r * APH + c8 * 8], g_Xhi + (m0 + r) * NHID + st * 32 + c8 * 8, av);
            cp_async16(&Al[r * APH + c8 * 8], g_Xlo + (m0 + r) * NHID + st * 32 + c8 * 8, av);
        }
    };

    unsigned smbase = (unsigned)__cvta_generic_to_shared(smh);
    // A frag ldmatrix offset: row = wm + (lane&15), kcol-half = (lane>>4)*8
    unsigned aoff = ((wm + (lane & 15)) * APH + ((lane >> 4) << 3)) * 2;
    // B frag ldmatrix offset (pitch BPH): row = wn + (lane&7) + ((lane>>4)<<3)
    unsigned boff = ((wn + (lane & 7) + ((lane >> 4) << 3)) * BPH + (((lane >> 3) & 1) << 3)) * 2;
    unsigned bBase = smbase + B_BASE_H * 2 + boff;

    load_B();
    load_A(0, 0);
    CP_COMMIT();                                 // G0 = {B, A0}
    load_A(1, 1);
    CP_COMMIT();                                 // G1 = {A1}

    for (int st = 0; st < 4; st++) {
        if (st < 3) { CP_WAIT(1); } else { CP_WAIT(0); }
        __syncthreads();

        unsigned aHi = smbase + (unsigned)((st & 1) * A_STAGE_H * 2) + aoff;
        unsigned aLo = aHi + A_BUF_H * 2;

#pragma unroll
        for (int ks = 0; ks < 2; ks++) {
            unsigned kbA = ks * 32;                          // within A stage
            unsigned kbBf = (unsigned)(st * 64 + ks * 32);   // within full-K B
            unsigned ah[2][4], al[2][4];
#pragma unroll
            for (int mi = 0; mi < 2; mi++) {
                LDSM4(ah[mi][0], ah[mi][1], ah[mi][2], ah[mi][3],
                      aHi + mi * (16 * APH * 2) + kbA);
                LDSM4(al[mi][0], al[mi][1], al[mi][2], al[mi][3],
                      aLo + mi * (16 * APH * 2) + kbA);
            }
#pragma unroll
            for (int p = 0; p < 4; p++) {
                unsigned bh[4], bl[4];
                LDSM4(bh[0], bh[1], bh[2], bh[3], bBase + p * (16 * BPH * 2) + kbBf);
                LDSM4(bl[0], bl[1], bl[2], bl[3], bBase + B_BUF_H * 2 + p * (16 * BPH * 2) + kbBf);
#pragma unroll
                for (int mi = 0; mi < 2; mi++) {
                    mma_f16(acc[mi][2 * p],     ah[mi], bh);
                    mma_f16(acc[mi][2 * p],     ah[mi], bl);
                    mma_f16(acc[mi][2 * p],     al[mi], bh);
                    mma_f16(acc[mi][2 * p + 1], ah[mi], bh + 2);
                    mma_f16(acc[mi][2 * p + 1], ah[mi], bl + 2);
                    mma_f16(acc[mi][2 * p + 1], al[mi], bh + 2);
                }
            }
        }
        __syncthreads();
        if (st < 2) {                     // A(st+2) into buffer (st&1), now free
            load_A(st & 1, st + 2);
            CP_COMMIT();
        }
    }

    float* sAs = (float*)smh;
    float* sAd = ((float*)smh) + 256;

    float attS[16], attD[16];
#pragma unroll
    for (int ni = 0; ni < 8; ni++) {
        int c = n0 + wn + ni * 8 + 2 * q;
        attS[2 * ni] = att_src[c];     attS[2 * ni + 1] = att_src[c + 1];
        attD[2 * ni] = att_dst[c];     attD[2 * ni + 1] = att_dst[c + 1];
    }
#pragma unroll
    for (int mi = 0; mi < 2; mi++) {
        float s1a = 0.f, s2a = 0.f, s1b = 0.f, s2b = 0.f;
#pragma unroll
        for (int ni = 0; ni < 8; ni++) {
            s1a += acc[mi][ni][0] * attS[2 * ni] + acc[mi][ni][1] * attS[2 * ni + 1];
            s2a += acc[mi][ni][0] * attD[2 * ni] + acc[mi][ni][1] * attD[2 * ni + 1];
            s1b += acc[mi][ni][2] * attS[2 * ni] + acc[mi][ni][3] * attS[2 * ni + 1];
            s2b += acc[mi][ni][2] * attD[2 * ni] + acc[mi][ni][3] * attD[2 * ni + 1];
        }
#pragma unroll
        for (int o = 2; o; o >>= 1) {
            s1a += __shfl_down_sync(0xffffffffu, s1a, o, 4);
            s2a += __shfl_down_sync(0xffffffffu, s2a, o, 4);
            s1b += __shfl_down_sync(0xffffffffu, s1b, o, 4);
            s2b += __shfl_down_sync(0xffffffffu, s2b, o, 4);
        }
        if (q == 0) {
            int half = warp & 1;
            int rA = wm + mi * 16 + g;
            sAs[half * 128 + rA] = s1a;      sAd[half * 128 + rA] = s2a;
            sAs[half * 128 + rA + 8] = s1b;  sAd[half * 128 + rA + 8] = s2b;
        }
    }
    __syncthreads();
    if (tid < 128) {
        int r = m0 + tid;
        if (r < N_NODES) {
            g_as[r * HEADS + head] = sAs[tid] + sAs[128 + tid];
            g_ad[r * HEADS + head] = sAd[tid] + sAd[128 + tid];
        }
    }

#pragma unroll
    for (int mi = 0; mi < 2; mi++) {
        int r = m0 + wm + mi * 16 + g;
#pragma unroll
        for (int ni = 0; ni < 8; ni++) {
            int c = n0 + wn + ni * 8 + 2 * q;
            if (r < N_NODES)
                *((__half2*)(g_hh + r * HC + c)) = __floats2half2_rn(acc[mi][ni][0], acc[mi][ni][1]);
            if (r + 8 < N_NODES)
                *((__half2*)(g_hh + (r + 8) * HC + c)) = __floats2half2_rn(acc[mi][ni][2], acc[mi][ni][3]);
        }
    }
}

// ------------------------- fused softmax + aggregate + GraphCON update --------
#define ACH 64
__global__ __launch_bounds__(64) void k_aggregate(const float* __restrict__ bias,
                                                  float* __restrict__ out, int layer) {
    __shared__ int   s_src[ACH];
    __shared__ float s_ex[ACH * 4];
    __shared__ float4 s_den[2];

    int n = blockIdx.x;
    int t = threadIdx.x;
    int hd = t >> 4;
    int wid = t >> 5, lane = t & 31;
    int st = g_off[n], en = g_off[n + 1];
    float4 ad4 = ((const float4*)g_ad)[n];
    const uint4* h16 = (const uint4*)g_hh;

    float4 denp = make_float4(0.f, 0.f, 0.f, 0.f);
    float a0 = 0.f, a1 = 0.f, a2 = 0.f, a3 = 0.f;
    float a4 = 0.f, a5 = 0.f, a6 = 0.f, a7 = 0.f;

#define ACCUM(u, e) { \
    float2 p0 = __half22float2(*(const __half2*)&u.x); \
    float2 p1 = __half22float2(*(const __half2*)&u.y); \
    float2 p2 = __half22float2(*(const __half2*)&u.z); \
    float2 p3 = __half22float2(*(const __half2*)&u.w); \
    a0 += e * p0.x; a1 += e * p0.y; a2 += e * p1.x; a3 += e * p1.y; \
    a4 += e * p2.x; a5 += e * p2.y; a6 += e * p3.x; a7 += e * p3.y; }

    for (int c0 = st; c0 < en; c0 += ACH) {
        int cl = en - c0; if (cl > ACH) cl = ACH;
        if (t < cl) {
            int s = g_csr_src[c0 + t];
            float4 as4 = ((const float4*)g_as)[s];
            float e0 = as4.x + ad4.x, e1 = as4.y + ad4.y;
            float e2 = as4.z + ad4.z, e3 = as4.w + ad4.w;
            e0 = e0 > 0.f ? e0 : e0 * NEG_SLOPE;
            e1 = e1 > 0.f ? e1 : e1 * NEG_SLOPE;
            e2 = e2 > 0.f ? e2 : e2 * NEG_SLOPE;
            e3 = e3 > 0.f ? e3 : e3 * NEG_SLOPE;
            float x0 = __expf(e0), x1 = __expf(e1), x2 = __expf(e2), x3 = __expf(e3);
            s_src[t] = s;
            ((float4*)s_ex)[t] = make_float4(x0, x1, x2, x3);
            denp.x += x0; denp.y += x1; denp.z += x2; denp.w += x3;
        }
        __syncthreads();
        int j = 0;
        for (; j + 8 <= cl; j += 8) {
            int ss[8]; float ee[8]; uint4 uu[8];
#pragma unroll
            for (int u = 0; u < 8; u++) {
                ss[u] = s_src[j + u];
                ee[u] = s_ex[(j + u) * 4 + hd];
            }
#pragma unroll
            for (int u = 0; u < 8; u++) uu[u] = h16[ss[u] * 64 + t];
#pragma unroll
            for (int u = 0; u < 8; u++) ACCUM(uu[u], ee[u])
        }
        for (; j < cl; j++) {
            int s = s_src[j];
            float e = s_ex[j * 4 + hd];
            uint4 u = h16[s * 64 + t];
            ACCUM(u, e)
        }
        __syncthreads();
    }
#undef ACCUM

#pragma unroll
    for (int o = 16; o; o >>= 1) {
        denp.x += __shfl_xor_sync(0xffffffffu, denp.x, o);
        denp.y += __shfl_xor_sync(0xffffffffu, denp.y, o);
        denp.z += __shfl_xor_sync(0xffffffffu, denp.z, o);
        denp.w += __shfl_xor_sync(0xffffffffu, denp.w, o);
    }
    if (lane == 0) s_den[wid] = denp;
    __syncthreads();
    float4 d0 = s_den[0], d1 = s_den[1];
    float dens[4] = {d0.x + d1.x, d0.y + d1.y, d0.z + d1.z, d0.w + d1.w};
    float inv = 1.0f / dens[hd];

    const float4* b4p = (const float4*)(bias + 8 * t);
    float4 b0 = b4p[0], b1 = b4p[1];
    float g0 = a0 * inv + b0.x, g1 = a1 * inv + b0.y;
    float g2 = a2 * inv + b0.z, g3 = a3 * inv + b0.w;
    float g4 = a4 * inv + b1.x, g5 = a5 * inv + b1.y;
    float g6 = a6 * inv + b1.z, g7 = a7 * inv + b1.w;
    g0 = g0 > 0.f ? g0 : (__expf(g0) - 1.f);
    g1 = g1 > 0.f ? g1 : (__expf(g1) - 1.f);
    g2 = g2 > 0.f ? g2 : (__expf(g2) - 1.f);
    g3 = g3 > 0.f ? g3 : (__expf(g3) - 1.f);
    g4 = g4 > 0.f ? g4 : (__expf(g4) - 1.f);
    g5 = g5 > 0.f ? g5 : (__expf(g5) - 1.f);
    g6 = g6 > 0.f ? g6 : (__expf(g6) - 1.f);
    g7 = g7 > 0.f ? g7 : (__expf(g7) - 1.f);
    float aggA = 0.25f * (g0 + g1 + g2 + g3);
    float aggB = 0.25f * (g4 + g5 + g6 + g7);

    float2 xv = *((const float2*)(g_X + n * NHID + 2 * t));
    float2 yv = *((const float2*)(g_Y + n * NHID + 2 * t));
    float y2a = yv.x + DT * (aggA - ALPHA * yv.x - GAMMA * xv.x);
    float y2b = yv.y + DT * (aggB - ALPHA * yv.y - GAMMA * xv.y);
    float x2a = xv.x + DT * y2a;
    float x2b = xv.y + DT * y2b;
    *((float2*)(g_X + n * NHID + 2 * t)) = make_float2(x2a, x2b);
    *((float2*)(g_Y + n * NHID + 2 * t)) = make_float2(y2a, y2b);

    __half hA = __float2half_rn(x2a), hB = __float2half_rn(x2b);
    __half lA = __float2half_rn(x2a - __half2float(hA));
    __half lB = __float2half_rn(x2b - __half2float(hB));
    *((__half2*)(g_Xhi + n * NHID + 2 * t)) = __halves2half2(hA, hB);
    *((__half2*)(g_Xlo + n * NHID + 2 * t)) = __halves2half2(lA, lB);

    float* xo = out + XALL_OFF + n * LSTRIDE + (layer + 1) * NHID + 2 * t;
    float* yo = out + YALL_OFF + n * LSTRIDE + (layer + 1) * NHID + 2 * t;
    *((float2*)xo) = make_float2(x2a, x2b);
    *((float2*)yo) = make_float2(y2a, y2b);
}

// ------------------------- output projection ----------------------------------
__global__ void k_outproj(const float* __restrict__ Wr, const float* __restrict__ br,
                          float* __restrict__ out) {
    __shared__ float xs[NHID];
    int n = blockIdx.x;
    int t = threadIdx.x;
    xs[t] = g_X[n * NHID + t];
    __syncthreads();
    if (t < NCLASS) {
        const float* w = Wr + t * NHID;
        float acc = 0.f;
#pragma unroll 8
        for (int k = 0; k < NHID; k++) acc += xs[k] * w[k];
        out[OUT_OFF + n * NCLASS + t] = acc + br[t];
    }
}

// ------------------------- launch ---------------------------------------------
extern "C" void kernel_launch(void* const* d_in, const int* in_sizes, int n_in,
                              void* d_out, int out_size) {
    const float* x       = (const float*)d_in[0];
    const int*   src     = (const int*)d_in[1];
    const int*   dst     = (const int*)d_in[2];
    const float* W       = (const float*)d_in[3];
    const float* att_src = (const float*)d_in[4];
    const float* att_dst = (const float*)d_in[5];
    const float* bias    = (const float*)d_in[6];
    const float* Wr      = (const float*)d_in[7];
    const float* br      = (const float*)d_in[8];
    float* out = (float*)d_out;

    cudaFuncSetAttribute(k_gemm, cudaFuncAttributeMaxDynamicSharedMemorySize, GEMM_SMEM);

    dim3 ggrid(HC / GBN, (N_NODES + GBM - 1) / GBM);   // (4, 157)

    // k_gemm in the profiled 4th slot
    k_splitW<<<(NHID * HC) / 256, 256>>>(W);                 // 1
    k_setup<<<N_NODES, NHID>>>(x, out);                      // 2
    k_csr<<<CSR_BLOCKS, CSR_THREADS>>>(src, dst);            // 3
    k_gemm<<<ggrid, 256, GEMM_SMEM>>>(att_src, att_dst);     // 4 (layer 0) <- profiled
    k_aggregate<<<N_NODES, 64>>>(bias, out, 0);              // 5 (layer 0)

    for (int l = 1; l < NLAYERS; l++) {
        k_gemm<<<ggrid, 256, GEMM_SMEM>>>(att_src, att_dst);
        k_aggregate<<<N_NODES, 64>>>(bias, out, l);
    }
    k_outproj<<<N_NODES, 128>>>(Wr, br, out);
}